// round 5
// baseline (speedup 1.0000x reference)
#include <cuda_runtime.h>
#include <cuda_bf16.h>
#include <cstdint>

#define BB    4
#define LQ    256
#define LK    2048
#define HIDD  1024
#define NH    16
#define DD    64
#define QT    16                     /* q rows per CTA */
#define NT    512                    /* threads per CTA */

#define CENTER_C      72.21632f
#define INV_SCALING_C 0.14662718f

typedef unsigned long long u64;
#define ABSM 0x7FFFFFFF7FFFFFFFULL

__device__ float g_VT[(size_t)BB * NH * DD * LK];   // V transposed [b,h,d,k]

__device__ __forceinline__ u64 fadd2(u64 a, u64 b) {
    u64 r; asm("add.rn.f32x2 %0, %1, %2;" : "=l"(r) : "l"(a), "l"(b)); return r;
}
__device__ __forceinline__ u64 ffma2(u64 a, u64 b, u64 c) {
    u64 r; asm("fma.rn.f32x2 %0, %1, %2, %3;" : "=l"(r) : "l"(a), "l"(b), "l"(c)); return r;
}
__device__ __forceinline__ float2 upk2(u64 a) {
    float2 f; asm("mov.b64 {%0, %1}, %2;" : "=f"(f.x), "=f"(f.y) : "l"(a)); return f;
}
__device__ __forceinline__ void cp16(uint32_t dst, const void* src) {
    asm volatile("cp.async.cg.shared.global [%0], [%1], 16;" :: "r"(dst), "l"(src));
}

// ---------------------------------------------------------------------------
// Kernel 0: transpose V -> VT[b,h,d,k].
// ---------------------------------------------------------------------------
__global__ __launch_bounds__(256) void k_vtrans(const float* __restrict__ Vg)
{
    __shared__ float t[64][65];
    const int bh = blockIdx.y, b = bh >> 4, h = bh & 15;
    const int k0 = blockIdx.x * 64;
    const int tid = threadIdx.x;
    #pragma unroll
    for (int r = 0; r < 4; r++) {
        int i = tid + 256 * r; int kr = i >> 4, g = i & 15;
        float4 v = *(const float4*)(Vg + ((size_t)(b * LK + k0 + kr)) * HIDD + h * DD + 4 * g);
        t[kr][4 * g + 0] = v.x; t[kr][4 * g + 1] = v.y;
        t[kr][4 * g + 2] = v.z; t[kr][4 * g + 3] = v.w;
    }
    __syncthreads();
    #pragma unroll
    for (int r = 0; r < 4; r++) {
        int i = tid + 256 * r; int d = i >> 4, g = i & 15;
        float4 o = make_float4(t[4 * g + 0][d], t[4 * g + 1][d], t[4 * g + 2][d], t[4 * g + 3][d]);
        *(float4*)(g_VT + ((size_t)(bh * DD + d)) * LK + k0 + 4 * g) = o;
    }
}

// ---------------------------------------------------------------------------
// Fused kernel. grid (LQ/16, NH, BB), block 512 (16 warps), ~201KB smem.
// Warp decomposition: kg = w&3 (32 k's), qg = w>>2 (4 q rows).
//   SMEM floats: [0,32768)      ebuf 16q x 2048k
//                [32768,49152)  staging: K (ph1) / V^T (ph2), 2 x 8192 halves
//                [49152,50176)  qbuf (negated Q)
//                [50176,50240)  dbuf (diag)
//                [50240,50256)  invs
//                [50256,50320)  part (16q x 4kg)
// ---------------------------------------------------------------------------
__global__ __launch_bounds__(NT) void k_fused(
    const float* __restrict__ Qg, const float* __restrict__ Kg,
    const float* __restrict__ diag,
    float* __restrict__ attn, float* __restrict__ out0)
{
    extern __shared__ float smem[];
    float* ebuf = smem;
    float* qbuf = smem + 49152;
    float* dbuf = smem + 50176;
    float* invs = smem + 50240;
    float* part = smem + 50256;

    const int b  = blockIdx.z, h = blockIdx.y;
    const int q0 = blockIdx.x * QT;
    const int tid = threadIdx.x, w = tid >> 5, lane = tid & 31;
    const int kg = w & 3, qg = w >> 2;          // k-group (32k), q-group (4q)
    const int s  = lane & 7;
    const uint32_t sbase = (uint32_t)__cvta_generic_to_shared(smem);
    const uint32_t stg_b = sbase + 32768u * 4u;

    // ---- prologue --------------------------------------------------------
    if (tid < 16)
        ((float4*)dbuf)[tid] = ((const float4*)(diag + h * DD))[tid];
    if (tid < 256) {                            // 16 rows x 16 f4, negated
        int qr = tid >> 4, g = tid & 15;
        float4 v = ((const float4*)(Qg + ((size_t)(b * LQ + q0 + qr)) * HIDD + h * DD))[g];
        ((float4*)qbuf)[qr * 16 + g] = make_float4(-v.x, -v.y, -v.z, -v.w);
    }

    // prefetch K chunk 0 (XOR-swizzled f4 rows: 128 k-rows x 16 f4)
    #pragma unroll
    for (int r = 0; r < 4; r++) {
        int i = tid + NT * r; int kr = i >> 4, g = i & 15;
        cp16(stg_b + (uint32_t)((kr * 16 + (g ^ (kr & 7))) * 16),
             ((const float4*)(Kg + ((size_t)(b * LK + kr)) * HIDD + h * DD)) + g);
    }
    asm volatile("cp.async.commit_group;");

    const ulonglong2* qb2 = (const ulonglong2*)qbuf;
    const ulonglong2* db2 = (const ulonglong2*)dbuf;
    float sume[4] = {0.f, 0.f, 0.f, 0.f};

    // ==== Phase 1: L1 distance -> e into ebuf =============================
    for (int c = 0; c < 16; c++) {
        if (c + 1 < 16) {
            uint32_t boff = (uint32_t)(((c + 1) & 1) * 32768);
            #pragma unroll
            for (int r = 0; r < 4; r++) {
                int i = tid + NT * r; int kr = i >> 4, g = i & 15;
                cp16(stg_b + boff + (uint32_t)((kr * 16 + (g ^ (kr & 7))) * 16),
                     ((const float4*)(Kg + ((size_t)(b * LK + (c + 1) * 128 + kr)) * HIDD
                                      + h * DD)) + g);
            }
            asm volatile("cp.async.commit_group;");
            asm volatile("cp.async.wait_group 1;");
        } else {
            asm volatile("cp.async.wait_group 0;");
        }
        __syncthreads();

        const ulonglong2* kb2 = (const ulonglong2*)(smem + 32768 + (c & 1) * 8192);

        u64 acc[4];
        #pragma unroll
        for (int q = 0; q < 4; q++) acc[q] = 0ull;

        #pragma unroll 4
        for (int g = 0; g < 16; g++) {
            ulonglong2 kv = kb2[(kg * 32 + lane) * 16 + (g ^ s)];   // per-lane k
            ulonglong2 dv = db2[g];                                  // broadcast
            #pragma unroll
            for (int q = 0; q < 4; q++) {
                ulonglong2 qv = qb2[(qg * 4 + q) * 16 + g];          // broadcast
                u64 t0 = fadd2(kv.x, qv.x) & ABSM;   // |k - q| (q pre-negated)
                u64 t1 = fadd2(kv.y, qv.y) & ABSM;
                acc[q] = ffma2(dv.x, t0, acc[q]);
                acc[q] = ffma2(dv.y, t1, acc[q]);
            }
        }

        #pragma unroll
        for (int q = 0; q < 4; q++) {
            float2 a = upk2(acc[q]);
            float e = __expf((CENTER_C - (a.x + a.y)) * INV_SCALING_C);
            ebuf[(qg * 4 + q) * 2048 + c * 128 + kg * 32 + lane] = e;
            sume[q] += e;
        }
        __syncthreads();
    }

    // softmax partial sums per (q, kg)
    #pragma unroll
    for (int q = 0; q < 4; q++) {
        float ssum = sume[q];
        #pragma unroll
        for (int o = 16; o > 0; o >>= 1) ssum += __shfl_xor_sync(0xffffffffu, ssum, o);
        if (lane == 0) part[(qg * 4 + q) * 4 + kg] = ssum;
    }
    __syncthreads();
    if (tid < 16)
        invs[tid] = 1.f / (part[tid * 4] + part[tid * 4 + 1] +
                           part[tid * 4 + 2] + part[tid * 4 + 3]);

    // prefetch V^T chunk 0 (64 d-rows x 32 f4, swizzled)
    const float* vtb = g_VT + ((size_t)(b * NH + h)) * DD * LK;
    #pragma unroll
    for (int r = 0; r < 4; r++) {
        int j = tid + NT * r; int d = j >> 5, k4 = j & 31;
        cp16(stg_b + (uint32_t)((d * 32 + (k4 ^ (d & 7))) * 16),
             vtb + (size_t)d * LK + 4 * k4);
    }
    asm volatile("cp.async.commit_group;");

    // ==== Phase 2: p write + P@V ==========================================
    u64 acc2[4][2];
    #pragma unroll
    for (int q = 0; q < 4; q++) { acc2[q][0] = 0ull; acc2[q][1] = 0ull; }
    const size_t arow0 = (((size_t)(b * NH + h)) * LQ + q0) * (size_t)LK;

    for (int c = 0; c < 16; c++) {
        int kc = c * 128;
        if (c + 1 < 16) {
            uint32_t boff = (uint32_t)(((c + 1) & 1) * 32768);
            #pragma unroll
            for (int r = 0; r < 4; r++) {
                int j = tid + NT * r; int d = j >> 5, k4 = j & 31;
                cp16(stg_b + boff + (uint32_t)((d * 32 + (k4 ^ (d & 7))) * 16),
                     vtb + (size_t)d * LK + kc + 128 + 4 * k4);
            }
            asm volatile("cp.async.commit_group;");
            asm volatile("cp.async.wait_group 1;");
        } else {
            asm volatile("cp.async.wait_group 0;");
        }
        __syncthreads();   // also publishes invs on c==0

        // write p (coalesced STG.128): 512 f4 by 512 threads
        {
            int qq = tid >> 5, k4 = tid & 31;
            float4 e4 = *(const float4*)(ebuf + qq * 2048 + kc + 4 * k4);
            float iv = invs[qq];
            float4 p = make_float4(e4.x * iv, e4.y * iv, e4.z * iv, e4.w * iv);
            *(float4*)(attn + arow0 + (size_t)qq * LK + kc + 4 * k4) = p;
        }

        // P@V: warp covers k-quarter (8 f4), 4 q rows; lane = d (two halves)
        const float4* vb4 = ((const float4*)smem) + 8192 + (c & 1) * 2048;
        #pragma unroll
        for (int k4i = 0; k4i < 8; k4i++) {
            int kidx4 = kg * 8 + k4i;
            int sw = kidx4 ^ s;
            ulonglong2 v0 = *(const ulonglong2*)&vb4[lane * 32 + sw];
            ulonglong2 v1 = *(const ulonglong2*)&vb4[(lane + 32) * 32 + sw];
            #pragma unroll
            for (int q = 0; q < 4; q++) {
                ulonglong2 pp = *(const ulonglong2*)(ebuf + (qg * 4 + q) * 2048
                                                     + kc + kidx4 * 4);  // broadcast
                acc2[q][0] = ffma2(pp.x, v0.x, acc2[q][0]);
                acc2[q][0] = ffma2(pp.y, v0.y, acc2[q][0]);
                acc2[q][1] = ffma2(pp.x, v1.x, acc2[q][1]);
                acc2[q][1] = ffma2(pp.y, v1.y, acc2[q][1]);
            }
        }
        __syncthreads();
    }

    // reduce k-group partials in the (now free) staging area
    float* red = smem + 32768;
    #pragma unroll
    for (int q = 0; q < 4; q++) {
        float2 a0 = upk2(acc2[q][0]);
        float2 a1 = upk2(acc2[q][1]);
        red[kg * 1024 + (qg * 4 + q) * 64 + lane]      = a0.x + a0.y;
        red[kg * 1024 + (qg * 4 + q) * 64 + 32 + lane] = a1.x + a1.y;
    }
    __syncthreads();
    #pragma unroll
    for (int r = 0; r < 2; r++) {
        int j = tid + NT * r;                   // j = qq*64 + d
        int qq = j >> 6, d = j & 63;
        float v = red[j] + red[1024 + j] + red[2048 + j] + red[3072 + j];
        out0[((size_t)(b * LQ + q0 + qq)) * HIDD + h * DD + d] = v * invs[qq];
    }
}

#define SMEMF (50320 * 4)    /* 201280 B */

extern "C" void kernel_launch(void* const* d_in, const int* in_sizes, int n_in,
                              void* d_out, int out_size)
{
    const float* Qg = (const float*)d_in[0];
    const float* Kg = (const float*)d_in[1];
    const float* Vg = (const float*)d_in[2];
    const float* dg = (const float*)d_in[3];

    float* out0 = (float*)d_out;
    float* attn = out0 + (size_t)BB * LQ * HIDD;   // (output, attention) concat

    cudaFuncSetAttribute(k_fused, cudaFuncAttributeMaxDynamicSharedMemorySize, SMEMF);

    k_vtrans<<<dim3(LK / 64, BB * NH), 256>>>(Vg);
    k_fused<<<dim3(LQ / QT, NH, BB), NT, SMEMF>>>(Qg, Kg, dg, attn, out0);
}

// round 6
// speedup vs baseline: 1.0353x; 1.0353x over previous
#include <cuda_runtime.h>
#include <cuda_bf16.h>
#include <cstdint>

#define BB    4
#define LQ    256
#define LK    2048
#define HIDD  1024
#define NH    16
#define DD    64
#define QT    16                     /* q rows per CTA */
#define NT    512                    /* threads per CTA */

#define CENTER_C      72.21632f
#define INV_SCALING_C 0.14662718f

typedef unsigned long long u64;
#define ABSM 0x7FFFFFFF7FFFFFFFULL

__device__ float g_VT[(size_t)BB * NH * DD * LK];   // V transposed [b,h,d,k]

__device__ __forceinline__ u64 fadd2(u64 a, u64 b) {
    u64 r; asm("add.rn.f32x2 %0, %1, %2;" : "=l"(r) : "l"(a), "l"(b)); return r;
}
__device__ __forceinline__ u64 ffma2(u64 a, u64 b, u64 c) {
    u64 r; asm("fma.rn.f32x2 %0, %1, %2, %3;" : "=l"(r) : "l"(a), "l"(b), "l"(c)); return r;
}
__device__ __forceinline__ float2 upk2(u64 a) {
    float2 f; asm("mov.b64 {%0, %1}, %2;" : "=f"(f.x), "=f"(f.y) : "l"(a)); return f;
}
__device__ __forceinline__ void cp16(uint32_t dst, const void* src) {
    asm volatile("cp.async.cg.shared.global [%0], [%1], 16;" :: "r"(dst), "l"(src));
}

// ---------------------------------------------------------------------------
// Kernel 0: transpose V -> VT[b,h,d,k].
// ---------------------------------------------------------------------------
__global__ __launch_bounds__(256) void k_vtrans(const float* __restrict__ Vg)
{
    __shared__ float t[64][65];
    const int bh = blockIdx.y, b = bh >> 4, h = bh & 15;
    const int k0 = blockIdx.x * 64;
    const int tid = threadIdx.x;
    #pragma unroll
    for (int r = 0; r < 4; r++) {
        int i = tid + 256 * r; int kr = i >> 4, g = i & 15;
        float4 v = *(const float4*)(Vg + ((size_t)(b * LK + k0 + kr)) * HIDD + h * DD + 4 * g);
        t[kr][4 * g + 0] = v.x; t[kr][4 * g + 1] = v.y;
        t[kr][4 * g + 2] = v.z; t[kr][4 * g + 3] = v.w;
    }
    __syncthreads();
    #pragma unroll
    for (int r = 0; r < 4; r++) {
        int i = tid + 256 * r; int d = i >> 4, g = i & 15;
        float4 o = make_float4(t[4 * g + 0][d], t[4 * g + 1][d], t[4 * g + 2][d], t[4 * g + 3][d]);
        *(float4*)(g_VT + ((size_t)(bh * DD + d)) * LK + k0 + 4 * g) = o;
    }
}

// ---------------------------------------------------------------------------
// Fused kernel. grid (LQ/16, NH, BB), block 512 (16 warps), ~218KB smem.
// Phase 1 warp: kg = w&3 (32 k's), qg = (w>>2)&1 (8 q's), gg = w>>3 (d-half).
//   Each K element read by exactly 2 warps; d-halves combined via scratch.
// Phase 2 warp: kg2 = w&7 (16 k's), qg2 = w>>3 (8 q's), both d-halves in regs.
//   SMEM floats: [0,32768)      ebuf 16q x 2048k
//                [32768,49152)  staging (K/V^T, 2 x 8192 halves) / final red
//                [49152,50176)  qbuf   [50176,50240) dbuf
//                [50240,50256)  invs   [50256,50320) part
//                [50320,54416)  scratch (d-half partial dists, 2048 u64)
// ---------------------------------------------------------------------------
__global__ __launch_bounds__(NT) void k_fused(
    const float* __restrict__ Qg, const float* __restrict__ Kg,
    const float* __restrict__ diag,
    float* __restrict__ attn, float* __restrict__ out0)
{
    extern __shared__ float smem[];
    float* ebuf = smem;
    float* qbuf = smem + 49152;
    float* dbuf = smem + 50176;
    float* invs = smem + 50240;
    float* part = smem + 50256;
    u64*   scr  = (u64*)(smem + 50320);

    const int b  = blockIdx.z, h = blockIdx.y;
    const int q0 = blockIdx.x * QT;
    const int tid = threadIdx.x, w = tid >> 5, lane = tid & 31;
    const int kg = w & 3, qg = (w >> 2) & 1, gg = w >> 3;   // phase-1 roles
    const int s  = lane & 7;
    const uint32_t sbase = (uint32_t)__cvta_generic_to_shared(smem);
    const uint32_t stg_b = sbase + 32768u * 4u;

    // ---- prologue --------------------------------------------------------
    if (tid < 16)
        ((float4*)dbuf)[tid] = ((const float4*)(diag + h * DD))[tid];
    if (tid < 256) {                            // 16 rows x 16 f4, negated
        int qr = tid >> 4, g = tid & 15;
        float4 v = ((const float4*)(Qg + ((size_t)(b * LQ + q0 + qr)) * HIDD + h * DD))[g];
        ((float4*)qbuf)[qr * 16 + g] = make_float4(-v.x, -v.y, -v.z, -v.w);
    }

    // prefetch K chunk 0 (XOR-swizzled f4 rows: 128 k-rows x 16 f4)
    #pragma unroll
    for (int r = 0; r < 4; r++) {
        int i = tid + NT * r; int kr = i >> 4, g = i & 15;
        cp16(stg_b + (uint32_t)((kr * 16 + (g ^ (kr & 7))) * 16),
             ((const float4*)(Kg + ((size_t)(b * LK + kr)) * HIDD + h * DD)) + g);
    }
    asm volatile("cp.async.commit_group;");

    const ulonglong2* qb2 = (const ulonglong2*)qbuf;
    const ulonglong2* db2 = (const ulonglong2*)dbuf;
    float sume[8] = {0.f, 0.f, 0.f, 0.f, 0.f, 0.f, 0.f, 0.f};
    const int gg8 = gg * 8;

    // ==== Phase 1: L1 distance -> e into ebuf =============================
    for (int c = 0; c < 16; c++) {
        if (c + 1 < 16) {
            uint32_t boff = (uint32_t)(((c + 1) & 1) * 32768);
            #pragma unroll
            for (int r = 0; r < 4; r++) {
                int i = tid + NT * r; int kr = i >> 4, g = i & 15;
                cp16(stg_b + boff + (uint32_t)((kr * 16 + (g ^ (kr & 7))) * 16),
                     ((const float4*)(Kg + ((size_t)(b * LK + (c + 1) * 128 + kr)) * HIDD
                                      + h * DD)) + g);
            }
            asm volatile("cp.async.commit_group;");
            asm volatile("cp.async.wait_group 1;");
        } else {
            asm volatile("cp.async.wait_group 0;");
        }
        __syncthreads();

        const ulonglong2* kb2 = (const ulonglong2*)(smem + 32768 + (c & 1) * 8192);

        u64 acc[8];
        #pragma unroll
        for (int q = 0; q < 8; q++) acc[q] = 0ull;

        #pragma unroll
        for (int gi = 0; gi < 8; gi++) {
            int g = gg8 + gi;                                    // this warp's d-half
            ulonglong2 kv = kb2[(kg * 32 + lane) * 16 + (g ^ s)]; // per-lane k
            ulonglong2 dv = db2[g];                               // broadcast
            #pragma unroll
            for (int q = 0; q < 8; q++) {
                ulonglong2 qv = qb2[(qg * 8 + q) * 16 + g];       // broadcast
                u64 t0 = fadd2(kv.x, qv.x) & ABSM;   // |k - q| (q pre-negated)
                u64 t1 = fadd2(kv.y, qv.y) & ABSM;
                acc[q] = ffma2(dv.x, t0, acc[q]);
                acc[q] = ffma2(dv.y, t1, acc[q]);
            }
        }

        if (gg == 1) {                 // publish upper-d partials
            u64* sc = scr + (w - 8) * 256 + lane;
            #pragma unroll
            for (int q = 0; q < 8; q++) sc[q * 32] = acc[q];
        }
        __syncthreads();
        if (gg == 0) {                 // combine halves, exp, store e
            const u64* sc = scr + w * 256 + lane;
            #pragma unroll
            for (int q = 0; q < 8; q++) {
                u64 a = fadd2(acc[q], sc[q * 32]);
                float2 f = upk2(a);
                float e = __expf((CENTER_C - (f.x + f.y)) * INV_SCALING_C);
                ebuf[(qg * 8 + q) * 2048 + c * 128 + kg * 32 + lane] = e;
                sume[q] += e;
            }
        }
    }

    // softmax partial sums per (q, kg) from gg0 warps
    if (gg == 0) {
        #pragma unroll
        for (int q = 0; q < 8; q++) {
            float ssum = sume[q];
            #pragma unroll
            for (int o = 16; o > 0; o >>= 1) ssum += __shfl_xor_sync(0xffffffffu, ssum, o);
            if (lane == 0) part[(qg * 8 + q) * 4 + kg] = ssum;
        }
    }
    __syncthreads();
    if (tid < 16)
        invs[tid] = 1.f / (part[tid * 4] + part[tid * 4 + 1] +
                           part[tid * 4 + 2] + part[tid * 4 + 3]);

    // prefetch V^T chunk 0 (64 d-rows x 32 f4, swizzled)
    const float* vtb = g_VT + ((size_t)(b * NH + h)) * DD * LK;
    #pragma unroll
    for (int r = 0; r < 4; r++) {
        int j = tid + NT * r; int d = j >> 5, k4 = j & 31;
        cp16(stg_b + (uint32_t)((d * 32 + (k4 ^ (d & 7))) * 16),
             vtb + (size_t)d * LK + 4 * k4);
    }
    asm volatile("cp.async.commit_group;");

    // ==== Phase 2: p write + P@V ==========================================
    const int kg2 = w & 7, qg2 = w >> 3;
    u64 acc2[8][2];
    #pragma unroll
    for (int q = 0; q < 8; q++) { acc2[q][0] = 0ull; acc2[q][1] = 0ull; }
    const size_t arow0 = (((size_t)(b * NH + h)) * LQ + q0) * (size_t)LK;

    for (int c = 0; c < 16; c++) {
        int kc = c * 128;
        if (c + 1 < 16) {
            uint32_t boff = (uint32_t)(((c + 1) & 1) * 32768);
            #pragma unroll
            for (int r = 0; r < 4; r++) {
                int j = tid + NT * r; int d = j >> 5, k4 = j & 31;
                cp16(stg_b + boff + (uint32_t)((d * 32 + (k4 ^ (d & 7))) * 16),
                     vtb + (size_t)d * LK + kc + 128 + 4 * k4);
            }
            asm volatile("cp.async.commit_group;");
            asm volatile("cp.async.wait_group 1;");
        } else {
            asm volatile("cp.async.wait_group 0;");
        }
        __syncthreads();   // also publishes invs on c==0

        // write p (coalesced STG.128): 512 f4 by 512 threads
        {
            int qq = tid >> 5, k4 = tid & 31;
            float4 e4 = *(const float4*)(ebuf + qq * 2048 + kc + 4 * k4);
            float iv = invs[qq];
            float4 p = make_float4(e4.x * iv, e4.y * iv, e4.z * iv, e4.w * iv);
            *(float4*)(attn + arow0 + (size_t)qq * LK + kc + 4 * k4) = p;
        }

        // P@V: warp covers its k-eighth (4 f4), 8 q rows, both d-halves
        const float4* vb4 = ((const float4*)smem) + 8192 + (c & 1) * 2048;
        #pragma unroll
        for (int k4i = 0; k4i < 4; k4i++) {
            int kidx4 = kg2 * 4 + k4i;
            int sw = kidx4 ^ s;
            ulonglong2 v0 = *(const ulonglong2*)&vb4[lane * 32 + sw];
            ulonglong2 v1 = *(const ulonglong2*)&vb4[(lane + 32) * 32 + sw];
            #pragma unroll
            for (int q = 0; q < 8; q++) {
                ulonglong2 pp = *(const ulonglong2*)(ebuf + (qg2 * 8 + q) * 2048
                                                     + kc + kidx4 * 4);  // broadcast
                acc2[q][0] = ffma2(pp.x, v0.x, acc2[q][0]);
                acc2[q][0] = ffma2(pp.y, v0.y, acc2[q][0]);
                acc2[q][1] = ffma2(pp.x, v1.x, acc2[q][1]);
                acc2[q][1] = ffma2(pp.y, v1.y, acc2[q][1]);
            }
        }
        __syncthreads();
    }

    // reduce k-eighth partials in the (now free) staging area: red[8][16q][64d]
    float* red = smem + 32768;
    #pragma unroll
    for (int q = 0; q < 8; q++) {
        float2 a0 = upk2(acc2[q][0]);
        float2 a1 = upk2(acc2[q][1]);
        red[kg2 * 1024 + (qg2 * 8 + q) * 64 + lane]      = a0.x + a0.y;
        red[kg2 * 1024 + (qg2 * 8 + q) * 64 + 32 + lane] = a1.x + a1.y;
    }
    __syncthreads();
    #pragma unroll
    for (int r = 0; r < 2; r++) {
        int j = tid + NT * r;                   // j = qq*64 + d
        int qq = j >> 6, d = j & 63;
        float v = red[j]        + red[1024 + j] + red[2048 + j] + red[3072 + j]
                + red[4096 + j] + red[5120 + j] + red[6144 + j] + red[7168 + j];
        out0[((size_t)(b * LQ + q0 + qq)) * HIDD + h * DD + d] = v * invs[qq];
    }
}

#define SMEMF (54416 * 4)    /* 217664 B */

extern "C" void kernel_launch(void* const* d_in, const int* in_sizes, int n_in,
                              void* d_out, int out_size)
{
    const float* Qg = (const float*)d_in[0];
    const float* Kg = (const float*)d_in[1];
    const float* Vg = (const float*)d_in[2];
    const float* dg = (const float*)d_in[3];

    float* out0 = (float*)d_out;
    float* attn = out0 + (size_t)BB * LQ * HIDD;   // (output, attention) concat

    cudaFuncSetAttribute(k_fused, cudaFuncAttributeMaxDynamicSharedMemorySize, SMEMF);

    k_vtrans<<<dim3(LK / 64, BB * NH), 256>>>(Vg);
    k_fused<<<dim3(LQ / QT, NH, BB), NT, SMEMF>>>(Qg, Kg, dg, attn, out0);
}

// round 7
// speedup vs baseline: 1.1213x; 1.0831x over previous
#include <cuda_runtime.h>
#include <cuda_bf16.h>
#include <cstdint>

#define BB    4
#define LQ    256
#define LK    2048
#define HIDD  1024
#define NH    16
#define DD    64
#define QT    16                     /* q rows per CTA */
#define NT    256                    /* threads per CTA */

#define CENTER_C      72.21632f
#define INV_SCALING_C 0.14662718f

typedef unsigned long long u64;
#define ABSM 0x7FFFFFFF7FFFFFFFULL

__device__ float g_VT[(size_t)BB * NH * DD * LK];   // V transposed [b,h,d,k]

__device__ __forceinline__ u64 fadd2(u64 a, u64 b) {
    u64 r; asm("add.rn.f32x2 %0, %1, %2;" : "=l"(r) : "l"(a), "l"(b)); return r;
}
__device__ __forceinline__ u64 ffma2(u64 a, u64 b, u64 c) {
    u64 r; asm("fma.rn.f32x2 %0, %1, %2, %3;" : "=l"(r) : "l"(a), "l"(b), "l"(c)); return r;
}
__device__ __forceinline__ float2 upk2(u64 a) {
    float2 f; asm("mov.b64 {%0, %1}, %2;" : "=f"(f.x), "=f"(f.y) : "l"(a)); return f;
}
__device__ __forceinline__ void cp16(uint32_t dst, const void* src) {
    asm volatile("cp.async.cg.shared.global [%0], [%1], 16;" :: "r"(dst), "l"(src));
}

// ---------------------------------------------------------------------------
// Kernel 0: transpose V -> VT[b,h,d,k].
// ---------------------------------------------------------------------------
__global__ __launch_bounds__(256) void k_vtrans(const float* __restrict__ Vg)
{
    __shared__ float t[64][65];
    const int bh = blockIdx.y, b = bh >> 4, h = bh & 15;
    const int k0 = blockIdx.x * 64;
    const int tid = threadIdx.x;
    #pragma unroll
    for (int r = 0; r < 4; r++) {
        int i = tid + 256 * r; int kr = i >> 4, g = i & 15;
        float4 v = *(const float4*)(Vg + ((size_t)(b * LK + k0 + kr)) * HIDD + h * DD + 4 * g);
        t[kr][4 * g + 0] = v.x; t[kr][4 * g + 1] = v.y;
        t[kr][4 * g + 2] = v.z; t[kr][4 * g + 3] = v.w;
    }
    __syncthreads();
    #pragma unroll
    for (int r = 0; r < 4; r++) {
        int i = tid + 256 * r; int d = i >> 4, g = i & 15;
        float4 o = make_float4(t[4 * g + 0][d], t[4 * g + 1][d], t[4 * g + 2][d], t[4 * g + 3][d]);
        *(float4*)(g_VT + ((size_t)(bh * DD + d)) * LK + k0 + 4 * g) = o;
    }
}

// ---------------------------------------------------------------------------
// Fused kernel. grid (LQ/16, NH, BB), block 256 (8 warps), ~201KB smem.
// Phase 1: warp = kg (32 k's, lanes) x qg (8 q rows). Each lane holds its FULL
//   64-float K row in registers (loaded once per chunk); inner loop does only
//   broadcast qv/dv LDS + packed math. ONE barrier per chunk; math sync-free.
// Phase 2: warp = kg (32 k's) x qg (8 q rows), V in smem (R4 structure).
//   SMEM floats: [0,32768)      ebuf 16q x 2048k
//                [32768,49152)  staging (K/V^T, 2 x 8192 halves) / final red
//                [49152,50176)  qbuf   [50176,50240) dbuf
//                [50240,50256)  invs   [50256,50320) part
// ---------------------------------------------------------------------------
__global__ __launch_bounds__(NT) void k_fused(
    const float* __restrict__ Qg, const float* __restrict__ Kg,
    const float* __restrict__ diag,
    float* __restrict__ attn, float* __restrict__ out0)
{
    extern __shared__ float smem[];
    float* ebuf = smem;
    float* qbuf = smem + 49152;
    float* dbuf = smem + 50176;
    float* invs = smem + 50240;
    float* part = smem + 50256;

    const int b  = blockIdx.z, h = blockIdx.y;
    const int q0 = blockIdx.x * QT;
    const int tid = threadIdx.x, w = tid >> 5, lane = tid & 31;
    const int kg = w & 3, qg = w >> 2;          // k-group (32k), q-group (8q)
    const int s  = lane & 7;
    const uint32_t sbase = (uint32_t)__cvta_generic_to_shared(smem);
    const uint32_t stg_b = sbase + 32768u * 4u;

    // ---- prologue --------------------------------------------------------
    if (tid < 16)
        ((float4*)dbuf)[tid] = ((const float4*)(diag + h * DD))[tid];
    {
        int qr = tid >> 4, g = tid & 15;        // 16 rows x 16 f4, negated
        float4 v = ((const float4*)(Qg + ((size_t)(b * LQ + q0 + qr)) * HIDD + h * DD))[g];
        ((float4*)qbuf)[qr * 16 + g] = make_float4(-v.x, -v.y, -v.z, -v.w);
    }

    // prefetch K chunk 0 (XOR-swizzled f4 rows: 128 k-rows x 16 f4)
    #pragma unroll
    for (int r = 0; r < 8; r++) {
        int i = tid + NT * r; int kr = i >> 4, g = i & 15;
        cp16(stg_b + (uint32_t)((kr * 16 + (g ^ (kr & 7))) * 16),
             ((const float4*)(Kg + ((size_t)(b * LK + kr)) * HIDD + h * DD)) + g);
    }
    asm volatile("cp.async.commit_group;");

    const ulonglong2* qb2 = (const ulonglong2*)qbuf;
    const ulonglong2* db2 = (const ulonglong2*)dbuf;
    float sume[8] = {0.f, 0.f, 0.f, 0.f, 0.f, 0.f, 0.f, 0.f};
    const int krow16 = (kg * 32 + lane) * 16;

    // ==== Phase 1: one barrier per chunk; math entirely in registers ======
    for (int c = 0; c < 16; c++) {
        asm volatile("cp.async.wait_group 0;");
        __syncthreads();          // buf[c&1] full; everyone done with buf[(c+1)&1]

        if (c + 1 < 16) {         // prefetch next chunk into the other buffer
            uint32_t boff = (uint32_t)(((c + 1) & 1) * 32768);
            #pragma unroll
            for (int r = 0; r < 8; r++) {
                int i = tid + NT * r; int kr = i >> 4, g = i & 15;
                cp16(stg_b + boff + (uint32_t)((kr * 16 + (g ^ (kr & 7))) * 16),
                     ((const float4*)(Kg + ((size_t)(b * LK + (c + 1) * 128 + kr)) * HIDD
                                      + h * DD)) + g);
            }
            asm volatile("cp.async.commit_group;");
        }

        // pull this warp's K rows into registers (64 floats per lane)
        const ulonglong2* kb2 = (const ulonglong2*)(smem + 32768 + (c & 1) * 8192);
        ulonglong2 kvr[16];
        #pragma unroll
        for (int g = 0; g < 16; g++) kvr[g] = kb2[krow16 + (g ^ s)];

        u64 acc[8];
        #pragma unroll
        for (int q = 0; q < 8; q++) acc[q] = 0ull;

        #pragma unroll
        for (int g = 0; g < 16; g++) {
            ulonglong2 dv = db2[g];                              // broadcast
            #pragma unroll
            for (int q = 0; q < 8; q++) {
                ulonglong2 qv = qb2[(qg * 8 + q) * 16 + g];      // broadcast
                u64 t0 = fadd2(kvr[g].x, qv.x) & ABSM;  // |k - q| (q pre-negated)
                u64 t1 = fadd2(kvr[g].y, qv.y) & ABSM;
                acc[q] = ffma2(dv.x, t0, acc[q]);
                acc[q] = ffma2(dv.y, t1, acc[q]);
            }
        }

        #pragma unroll
        for (int q = 0; q < 8; q++) {
            float2 a = upk2(acc[q]);
            float e = __expf((CENTER_C - (a.x + a.y)) * INV_SCALING_C);
            ebuf[(qg * 8 + q) * 2048 + c * 128 + kg * 32 + lane] = e;
            sume[q] += e;
        }
        // no trailing barrier: next iteration's top barrier protects buffers
    }

    // softmax partial sums per (q, kg)
    #pragma unroll
    for (int q = 0; q < 8; q++) {
        float ssum = sume[q];
        #pragma unroll
        for (int o = 16; o > 0; o >>= 1) ssum += __shfl_xor_sync(0xffffffffu, ssum, o);
        if (lane == 0) part[(qg * 8 + q) * 4 + kg] = ssum;
    }
    __syncthreads();
    if (tid < 16)
        invs[tid] = 1.f / (part[tid * 4] + part[tid * 4 + 1] +
                           part[tid * 4 + 2] + part[tid * 4 + 3]);

    // prefetch V^T chunk 0 (64 d-rows x 32 f4, swizzled)
    const float* vtb = g_VT + ((size_t)(b * NH + h)) * DD * LK;
    #pragma unroll
    for (int r = 0; r < 8; r++) {
        int j = tid + NT * r; int d = j >> 5, k4 = j & 31;
        cp16(stg_b + (uint32_t)((d * 32 + (k4 ^ (d & 7))) * 16),
             vtb + (size_t)d * LK + 4 * k4);
    }
    asm volatile("cp.async.commit_group;");

    // ==== Phase 2: p write + P@V ==========================================
    u64 acc2[8][2];
    #pragma unroll
    for (int q = 0; q < 8; q++) { acc2[q][0] = 0ull; acc2[q][1] = 0ull; }
    const size_t arow0 = (((size_t)(b * NH + h)) * LQ + q0) * (size_t)LK;

    for (int c = 0; c < 16; c++) {
        int kc = c * 128;
        if (c + 1 < 16) {
            uint32_t boff = (uint32_t)(((c + 1) & 1) * 32768);
            #pragma unroll
            for (int r = 0; r < 8; r++) {
                int j = tid + NT * r; int d = j >> 5, k4 = j & 31;
                cp16(stg_b + boff + (uint32_t)((d * 32 + (k4 ^ (d & 7))) * 16),
                     vtb + (size_t)d * LK + kc + 128 + 4 * k4);
            }
            asm volatile("cp.async.commit_group;");
            asm volatile("cp.async.wait_group 1;");
        } else {
            asm volatile("cp.async.wait_group 0;");
        }
        __syncthreads();   // also publishes invs on c==0

        // write p (coalesced STG.128): 512 f4 by 256 threads
        #pragma unroll
        for (int r = 0; r < 2; r++) {
            int j = tid + NT * r; int qq = j >> 5, k4 = j & 31;
            float4 e4 = *(const float4*)(ebuf + qq * 2048 + kc + 4 * k4);
            float iv = invs[qq];
            float4 p = make_float4(e4.x * iv, e4.y * iv, e4.z * iv, e4.w * iv);
            *(float4*)(attn + arow0 + (size_t)qq * LK + kc + 4 * k4) = p;
        }

        // P@V: warp covers k-quarter (8 f4), 8 q rows; lane = d (two halves)
        const float4* vb4 = ((const float4*)smem) + 8192 + (c & 1) * 2048;
        #pragma unroll
        for (int k4i = 0; k4i < 8; k4i++) {
            int kidx4 = kg * 8 + k4i;
            int sw = kidx4 ^ s;
            ulonglong2 v0 = *(const ulonglong2*)&vb4[lane * 32 + sw];
            ulonglong2 v1 = *(const ulonglong2*)&vb4[(lane + 32) * 32 + sw];
            #pragma unroll
            for (int q = 0; q < 8; q++) {
                ulonglong2 pp = *(const ulonglong2*)(ebuf + (qg * 8 + q) * 2048
                                                     + kc + kidx4 * 4);  // broadcast
                acc2[q][0] = ffma2(pp.x, v0.x, acc2[q][0]);
                acc2[q][0] = ffma2(pp.y, v0.y, acc2[q][0]);
                acc2[q][1] = ffma2(pp.x, v1.x, acc2[q][1]);
                acc2[q][1] = ffma2(pp.y, v1.y, acc2[q][1]);
            }
        }
        __syncthreads();
    }

    // reduce k-group partials in the (now free) staging area: red[4][16q][64d]
    float* red = smem + 32768;
    #pragma unroll
    for (int q = 0; q < 8; q++) {
        float2 a0 = upk2(acc2[q][0]);
        float2 a1 = upk2(acc2[q][1]);
        red[kg * 1024 + (qg * 8 + q) * 64 + lane]      = a0.x + a0.y;
        red[kg * 1024 + (qg * 8 + q) * 64 + 32 + lane] = a1.x + a1.y;
    }
    __syncthreads();
    #pragma unroll
    for (int r = 0; r < 4; r++) {
        int j = tid + NT * r;                   // j = qq*64 + d
        int qq = j >> 6, d = j & 63;
        float v = red[j] + red[1024 + j] + red[2048 + j] + red[3072 + j];
        out0[((size_t)(b * LQ + q0 + qq)) * HIDD + h * DD + d] = v * invs[qq];
    }
}

#define SMEMF (50320 * 4)    /* 201280 B */

extern "C" void kernel_launch(void* const* d_in, const int* in_sizes, int n_in,
                              void* d_out, int out_size)
{
    const float* Qg = (const float*)d_in[0];
    const float* Kg = (const float*)d_in[1];
    const float* Vg = (const float*)d_in[2];
    const float* dg = (const float*)d_in[3];

    float* out0 = (float*)d_out;
    float* attn = out0 + (size_t)BB * LQ * HIDD;   // (output, attention) concat

    cudaFuncSetAttribute(k_fused, cudaFuncAttributeMaxDynamicSharedMemorySize, SMEMF);

    k_vtrans<<<dim3(LK / 64, BB * NH), 256>>>(Vg);
    k_fused<<<dim3(LQ / QT, NH, BB), NT, SMEMF>>>(Qg, Kg, dg, attn, out0);
}

// round 8
// speedup vs baseline: 1.3014x; 1.1606x over previous
#include <cuda_runtime.h>
#include <cuda_bf16.h>
#include <cstdint>

#define BB    4
#define LQ    256
#define LK    2048
#define HIDD  1024
#define NH    16
#define DD    64
#define QT    16                     /* q rows per CTA */
#define NT    256                    /* threads per CTA */

#define CENTER_C      72.21632f
#define INV_SCALING_C 0.14662718f

typedef unsigned long long u64;
#define ABSM 0x7FFFFFFF7FFFFFFFULL

__device__ float g_VT[(size_t)BB * NH * DD * LK];   // V transposed [b,h,d,k]

__device__ __forceinline__ u64 fadd2(u64 a, u64 b) {
    u64 r; asm("add.rn.f32x2 %0, %1, %2;" : "=l"(r) : "l"(a), "l"(b)); return r;
}
__device__ __forceinline__ u64 ffma2(u64 a, u64 b, u64 c) {
    u64 r; asm("fma.rn.f32x2 %0, %1, %2, %3;" : "=l"(r) : "l"(a), "l"(b), "l"(c)); return r;
}
__device__ __forceinline__ float2 upk2(u64 a) {
    float2 f; asm("mov.b64 {%0, %1}, %2;" : "=f"(f.x), "=f"(f.y) : "l"(a)); return f;
}
__device__ __forceinline__ void cp16(uint32_t dst, const void* src) {
    asm volatile("cp.async.cg.shared.global [%0], [%1], 16;" :: "r"(dst), "l"(src));
}

// ---------------------------------------------------------------------------
// Kernel 0: transpose V -> VT[b,h,d,k].
// ---------------------------------------------------------------------------
__global__ __launch_bounds__(256) void k_vtrans(const float* __restrict__ Vg)
{
    __shared__ float t[64][65];
    const int bh = blockIdx.y, b = bh >> 4, h = bh & 15;
    const int k0 = blockIdx.x * 64;
    const int tid = threadIdx.x;
    #pragma unroll
    for (int r = 0; r < 4; r++) {
        int i = tid + 256 * r; int kr = i >> 4, g = i & 15;
        float4 v = *(const float4*)(Vg + ((size_t)(b * LK + k0 + kr)) * HIDD + h * DD + 4 * g);
        t[kr][4 * g + 0] = v.x; t[kr][4 * g + 1] = v.y;
        t[kr][4 * g + 2] = v.z; t[kr][4 * g + 3] = v.w;
    }
    __syncthreads();
    #pragma unroll
    for (int r = 0; r < 4; r++) {
        int i = tid + 256 * r; int d = i >> 4, g = i & 15;
        float4 o = make_float4(t[4 * g + 0][d], t[4 * g + 1][d], t[4 * g + 2][d], t[4 * g + 3][d]);
        *(float4*)(g_VT + ((size_t)(bh * DD + d)) * LK + k0 + 4 * g) = o;
    }
}

// ---------------------------------------------------------------------------
// Fused kernel. grid (LQ/16, NH, BB), block 256 (8 warps), ~85KB smem -> occ 2.
// Phase 1: warp = kg (32 k lanes) x qg (8 q rows), K rows register-resident;
//   e written UNNORMALIZED to attn gmem (stays L2-hot); sums in regs.
// Phase 2: streams V^T chunks AND e-chunks (cp.async from attn/L2) into smem;
//   writes p = e*inv back to attn; P@V from smem broadcasts.
//   SMEM floats: [0,16384)      K / V^T ring (2 x 8192)
//                [16384,20480)  e-stage ring (2 x 2048)
//                [20480,21504)  qbuf (negated Q)
//                [21504,21568)  dbuf  [21568,21584) invs  [21584,21712) part
//                final reduce reuses [0,8192)
// ---------------------------------------------------------------------------
__global__ __launch_bounds__(NT, 2) void k_fused(
    const float* __restrict__ Qg, const float* __restrict__ Kg,
    const float* __restrict__ diag,
    float* __restrict__ attn, float* __restrict__ out0)
{
    extern __shared__ float smem[];
    float* estg0 = smem + 16384;
    float* qbuf  = smem + 20480;
    float* dbuf  = smem + 21504;
    float* invs  = smem + 21568;
    float* part  = smem + 21584;

    const int b  = blockIdx.z, h = blockIdx.y;
    const int q0 = blockIdx.x * QT;
    const int tid = threadIdx.x, w = tid >> 5, lane = tid & 31;
    const int kg = w & 3, qg = w >> 2;          // k-group (32k), q-group (8q)
    const int s  = lane & 7;
    const uint32_t sbase = (uint32_t)__cvta_generic_to_shared(smem);
    const uint32_t estg_b = sbase + 16384u * 4u;

    const size_t arow0 = (((size_t)(b * NH + h)) * LQ + q0) * (size_t)LK;

    // ---- prologue --------------------------------------------------------
    if (tid < 16)
        ((float4*)dbuf)[tid] = ((const float4*)(diag + h * DD))[tid];
    {
        int qr = tid >> 4, g = tid & 15;        // 16 rows x 16 f4, negated
        float4 v = ((const float4*)(Qg + ((size_t)(b * LQ + q0 + qr)) * HIDD + h * DD))[g];
        ((float4*)qbuf)[qr * 16 + g] = make_float4(-v.x, -v.y, -v.z, -v.w);
    }

    // prefetch K chunk 0 (XOR-swizzled f4 rows: 128 k-rows x 16 f4)
    #pragma unroll
    for (int r = 0; r < 8; r++) {
        int i = tid + NT * r; int kr = i >> 4, g = i & 15;
        cp16(sbase + (uint32_t)((kr * 16 + (g ^ (kr & 7))) * 16),
             ((const float4*)(Kg + ((size_t)(b * LK + kr)) * HIDD + h * DD)) + g);
    }
    asm volatile("cp.async.commit_group;");

    const ulonglong2* qb2 = (const ulonglong2*)qbuf;
    const ulonglong2* db2 = (const ulonglong2*)dbuf;
    float sume[8] = {0.f, 0.f, 0.f, 0.f, 0.f, 0.f, 0.f, 0.f};
    const int krow16 = (kg * 32 + lane) * 16;

    // ==== Phase 1: one barrier per chunk; e -> gmem (unnormalized) ========
    for (int c = 0; c < 16; c++) {
        asm volatile("cp.async.wait_group 0;");
        __syncthreads();          // buf[c&1] full; everyone done with buf[(c+1)&1]

        if (c + 1 < 16) {         // prefetch next chunk into the other buffer
            uint32_t boff = (uint32_t)(((c + 1) & 1) * 32768);
            #pragma unroll
            for (int r = 0; r < 8; r++) {
                int i = tid + NT * r; int kr = i >> 4, g = i & 15;
                cp16(sbase + boff + (uint32_t)((kr * 16 + (g ^ (kr & 7))) * 16),
                     ((const float4*)(Kg + ((size_t)(b * LK + (c + 1) * 128 + kr)) * HIDD
                                      + h * DD)) + g);
            }
            asm volatile("cp.async.commit_group;");
        }

        // pull this warp's K rows into registers (64 floats per lane)
        const ulonglong2* kb2 = (const ulonglong2*)(smem + (c & 1) * 8192);
        ulonglong2 kvr[16];
        #pragma unroll
        for (int g = 0; g < 16; g++) kvr[g] = kb2[krow16 + (g ^ s)];

        u64 acc[8];
        #pragma unroll
        for (int q = 0; q < 8; q++) acc[q] = 0ull;

        #pragma unroll
        for (int g = 0; g < 16; g++) {
            ulonglong2 dv = db2[g];                              // broadcast
            #pragma unroll
            for (int q = 0; q < 8; q++) {
                ulonglong2 qv = qb2[(qg * 8 + q) * 16 + g];      // broadcast
                u64 t0 = fadd2(kvr[g].x, qv.x) & ABSM;  // |k - q| (q pre-negated)
                u64 t1 = fadd2(kvr[g].y, qv.y) & ABSM;
                acc[q] = ffma2(dv.x, t0, acc[q]);
                acc[q] = ffma2(dv.y, t1, acc[q]);
            }
        }

        #pragma unroll
        for (int q = 0; q < 8; q++) {
            float2 a = upk2(acc[q]);
            float e = __expf((CENTER_C - (a.x + a.y)) * INV_SCALING_C);
            attn[arow0 + (size_t)(qg * 8 + q) * LK + c * 128 + kg * 32 + lane] = e;
            sume[q] += e;
        }
    }

    // softmax partial sums per (q, kg)
    #pragma unroll
    for (int q = 0; q < 8; q++) {
        float ssum = sume[q];
        #pragma unroll
        for (int o = 16; o > 0; o >>= 1) ssum += __shfl_xor_sync(0xffffffffu, ssum, o);
        if (lane == 0) part[(qg * 8 + q) * 4 + kg] = ssum;
    }
    __syncthreads();   // e STGs + parts visible block-wide
    if (tid < 16)
        invs[tid] = 1.f / (part[tid * 4] + part[tid * 4 + 1] +
                           part[tid * 4 + 2] + part[tid * 4 + 3]);

    // prefetch V^T chunk 0 + e chunk 0
    const float* vtb = g_VT + ((size_t)(b * NH + h)) * DD * LK;
    #pragma unroll
    for (int r = 0; r < 8; r++) {
        int j = tid + NT * r; int d = j >> 5, k4 = j & 31;
        cp16(sbase + (uint32_t)((d * 32 + (k4 ^ (d & 7))) * 16),
             vtb + (size_t)d * LK + 4 * k4);
    }
    #pragma unroll
    for (int r = 0; r < 2; r++) {
        int j = tid + NT * r; int qq = j >> 5, k4 = j & 31;
        cp16(estg_b + (uint32_t)(j * 16),
             attn + arow0 + (size_t)qq * LK + 4 * k4);
    }
    asm volatile("cp.async.commit_group;");

    // ==== Phase 2: p write + P@V ==========================================
    u64 acc2[8][2];
    #pragma unroll
    for (int q = 0; q < 8; q++) { acc2[q][0] = 0ull; acc2[q][1] = 0ull; }

    for (int c = 0; c < 16; c++) {
        int kc = c * 128;
        if (c + 1 < 16) {
            uint32_t boff  = (uint32_t)(((c + 1) & 1) * 32768);
            uint32_t boffe = (uint32_t)(((c + 1) & 1) * 8192);
            #pragma unroll
            for (int r = 0; r < 8; r++) {
                int j = tid + NT * r; int d = j >> 5, k4 = j & 31;
                cp16(sbase + boff + (uint32_t)((d * 32 + (k4 ^ (d & 7))) * 16),
                     vtb + (size_t)d * LK + kc + 128 + 4 * k4);
            }
            #pragma unroll
            for (int r = 0; r < 2; r++) {
                int j = tid + NT * r; int qq = j >> 5, k4 = j & 31;
                cp16(estg_b + boffe + (uint32_t)(j * 16),
                     attn + arow0 + (size_t)qq * LK + kc + 128 + 4 * k4);
            }
            asm volatile("cp.async.commit_group;");
            asm volatile("cp.async.wait_group 1;");
        } else {
            asm volatile("cp.async.wait_group 0;");
        }
        __syncthreads();   // also publishes invs on c==0

        const float* estg = estg0 + (c & 1) * 2048;

        // write p = e * inv (read stage, coalesced STG.128)
        #pragma unroll
        for (int r = 0; r < 2; r++) {
            int j = tid + NT * r; int qq = j >> 5, k4 = j & 31;
            float4 e4 = *(const float4*)(estg + j * 4);
            float iv = invs[qq];
            float4 p = make_float4(e4.x * iv, e4.y * iv, e4.z * iv, e4.w * iv);
            *(float4*)(attn + arow0 + (size_t)qq * LK + kc + 4 * k4) = p;
        }

        // P@V: warp covers k-quarter (8 f4), 8 q rows; lane = d (two halves)
        const float4* vb4 = ((const float4*)smem) + (c & 1) * 2048;
        #pragma unroll
        for (int k4i = 0; k4i < 8; k4i++) {
            int kidx4 = kg * 8 + k4i;
            int sw = kidx4 ^ s;
            ulonglong2 v0 = *(const ulonglong2*)&vb4[lane * 32 + sw];
            ulonglong2 v1 = *(const ulonglong2*)&vb4[(lane + 32) * 32 + sw];
            #pragma unroll
            for (int q = 0; q < 8; q++) {
                ulonglong2 pp = *(const ulonglong2*)(estg + (qg * 8 + q) * 128
                                                     + kidx4 * 4);   // broadcast
                acc2[q][0] = ffma2(pp.x, v0.x, acc2[q][0]);
                acc2[q][0] = ffma2(pp.y, v0.y, acc2[q][0]);
                acc2[q][1] = ffma2(pp.x, v1.x, acc2[q][1]);
                acc2[q][1] = ffma2(pp.y, v1.y, acc2[q][1]);
            }
        }
        __syncthreads();
    }

    // reduce k-group partials in [0,8192): red[4][16q][64d]
    float* red = smem;
    #pragma unroll
    for (int q = 0; q < 8; q++) {
        float2 a0 = upk2(acc2[q][0]);
        float2 a1 = upk2(acc2[q][1]);
        red[kg * 1024 + (qg * 8 + q) * 64 + lane]      = a0.x + a0.y;
        red[kg * 1024 + (qg * 8 + q) * 64 + 32 + lane] = a1.x + a1.y;
    }
    __syncthreads();
    #pragma unroll
    for (int r = 0; r < 4; r++) {
        int j = tid + NT * r;                   // j = qq*64 + d
        int qq = j >> 6, d = j & 63;
        float v = red[j] + red[1024 + j] + red[2048 + j] + red[3072 + j];
        out0[((size_t)(b * LQ + q0 + qq)) * HIDD + h * DD + d] = v * invs[qq];
    }
}

#define SMEMF (21712 * 4)    /* 86848 B -> 2 CTAs/SM */

extern "C" void kernel_launch(void* const* d_in, const int* in_sizes, int n_in,
                              void* d_out, int out_size)
{
    const float* Qg = (const float*)d_in[0];
    const float* Kg = (const float*)d_in[1];
    const float* Vg = (const float*)d_in[2];
    const float* dg = (const float*)d_in[3];

    float* out0 = (float*)d_out;
    float* attn = out0 + (size_t)BB * LQ * HIDD;   // (output, attention) concat

    cudaFuncSetAttribute(k_fused, cudaFuncAttributeMaxDynamicSharedMemorySize, SMEMF);

    k_vtrans<<<dim3(LK / 64, BB * NH), 256>>>(Vg);
    k_fused<<<dim3(LQ / QT, NH, BB), NT, SMEMF>>>(Qg, Kg, dg, attn, out0);
}